// round 14
// baseline (speedup 1.0000x reference)
#include <cuda_runtime.h>
#include <cuda_fp16.h>
#include <cstdint>

#define SLEN 2048
#define DDIM 128
#define NB 16
#define TQ 64
#define TK 64
#define THREADS 128

// strides in halves
#define QS 136
#define KS 136
#define VS 136

// smem offsets in halves: K double + V double (Q in registers, staged via SK1)
#define SK0_H 0
#define SK1_H 8704
#define SV0_H 17408
#define SV1_H 26112
#define SMEM_BYTES (34816 * 2)     // 69632 B

static __device__ __half g_Qh[(size_t)NB * SLEN * DDIM];
static __device__ __half g_Th[(size_t)NB * SLEN * DDIM];
static __device__ __half g_Vh[(size_t)NB * SLEN * DDIM];

__device__ __forceinline__ uint32_t smem_u32(const void* p) {
    uint32_t a;
    asm("{ .reg .u64 t; cvta.to.shared.u64 t, %1; cvt.u32.u64 %0, t; }" : "=r"(a) : "l"(p));
    return a;
}
__device__ __forceinline__ void cp16(uint32_t dst, const void* src) {
    asm volatile("cp.async.cg.shared.global [%0], [%1], 16;" :: "r"(dst), "l"(src) : "memory");
}
#define CP_COMMIT() asm volatile("cp.async.commit_group;" ::: "memory")
#define CP_WAIT0()  asm volatile("cp.async.wait_group 0;" ::: "memory")

__device__ __forceinline__ void ldsm4(uint32_t* r, uint32_t a) {
    asm volatile("ldmatrix.sync.aligned.m8n8.x4.shared.b16 {%0,%1,%2,%3}, [%4];"
                 : "=r"(r[0]), "=r"(r[1]), "=r"(r[2]), "=r"(r[3]) : "r"(a));
}
__device__ __forceinline__ void ldsm4t(uint32_t* r, uint32_t a) {
    asm volatile("ldmatrix.sync.aligned.m8n8.x4.trans.shared.b16 {%0,%1,%2,%3}, [%4];"
                 : "=r"(r[0]), "=r"(r[1]), "=r"(r[2]), "=r"(r[3]) : "r"(a));
}
__device__ __forceinline__ void mma16(float* d, uint32_t a0, uint32_t a1, uint32_t a2,
                                      uint32_t a3, uint32_t b0, uint32_t b1) {
    asm volatile("mma.sync.aligned.m16n8k16.row.col.f32.f16.f16.f32 "
                 "{%0,%1,%2,%3}, {%4,%5,%6,%7}, {%8,%9}, {%0,%1,%2,%3};"
                 : "+f"(d[0]), "+f"(d[1]), "+f"(d[2]), "+f"(d[3])
                 : "r"(a0), "r"(a1), "r"(a2), "r"(a3), "r"(b0), "r"(b1));
}
__device__ __forceinline__ uint32_t ex2h2(uint32_t u) {
    uint32_t r;
    asm("ex2.approx.f16x2 %0, %1;" : "=r"(r) : "r"(u));
    return r;
}

#define CEXC 0.12751754f    // log2(e)/sqrt(128)
#define BIGNC (-30000.0f)

// ---------------- fused conversion pre-kernel (Q, T, V -> fp16) ----------------
__global__ void convAll(const float* __restrict__ Q, const float* __restrict__ T,
                        const float* __restrict__ V,
                        __half* __restrict__ Qh, __half* __restrict__ Th,
                        __half* __restrict__ Vh) {
    const float* s;
    __half* d;
    if (blockIdx.y == 0)      { s = Q; d = Qh; }
    else if (blockIdx.y == 1) { s = T; d = Th; }
    else                      { s = V; d = Vh; }
    int i = blockIdx.x * blockDim.x + threadIdx.x;    // i < n/8
    float4 v0 = ((const float4*)s)[2 * i + 0];
    float4 v1 = ((const float4*)s)[2 * i + 1];
    __half2 h0 = __floats2half2_rn(v0.x, v0.y);
    __half2 h1 = __floats2half2_rn(v0.z, v0.w);
    __half2 h2 = __floats2half2_rn(v1.x, v1.y);
    __half2 h3 = __floats2half2_rn(v1.z, v1.w);
    uint4 o = make_uint4(*(uint32_t*)&h0, *(uint32_t*)&h1,
                         *(uint32_t*)&h2, *(uint32_t*)&h3);
    ((uint4*)d)[i] = o;
}

// epilogue for one n-tile (8 cols): threshold + causal + f16x2 exp2
__device__ __forceinline__ void epi_nt(const float* Snt, int ktile, int nt, int qtv,
                                       int lr, int grlo, int grhi,
                                       uint32_t& plo, uint32_t& phi,
                                       __half2& accLo, __half2& accHi) {
    const int c = nt * 8 + lr * 2;
    const int gc = ktile * TK + c;
    const bool diag = (ktile == qtv);
    float l0 = (Snt[0] > 0.3f) ? Snt[0] * CEXC : 0.0f;
    float l1 = (Snt[1] > 0.3f) ? Snt[1] * CEXC : 0.0f;
    float l2 = (Snt[2] > 0.3f) ? Snt[2] * CEXC : 0.0f;
    float l3 = (Snt[3] > 0.3f) ? Snt[3] * CEXC : 0.0f;
    if (diag) {
        if (gc     > grlo) l0 = BIGNC;
        if (gc + 1 > grlo) l1 = BIGNC;
        if (gc     > grhi) l2 = BIGNC;
        if (gc + 1 > grhi) l3 = BIGNC;
    }
    __half2 hlo = __floats2half2_rn(l0, l1);
    __half2 hhi = __floats2half2_rn(l2, l3);
    plo = ex2h2(*(uint32_t*)&hlo);
    phi = ex2h2(*(uint32_t*)&hhi);
    accLo = __hadd2(accLo, *(__half2*)&plo);
    accHi = __hadd2(accHi, *(__half2*)&phi);
}

// ---------------- main attention kernel ----------------
__global__ __launch_bounds__(THREADS, 2)
void attn_h(const __half* __restrict__ Qh, const __half* __restrict__ Th,
            const __half* __restrict__ Vh, float* __restrict__ Og) {
    extern __shared__ __align__(16) char smraw[];
    const uint32_t sb = smem_u32(smraw);

    const int idx = blockIdx.x;
    const int qt = (SLEN / TQ - 1) - (idx >> 4);   // LPT: heavy first
    const int b = idx & 15;

    const int tid = threadIdx.x;
    const int warp = tid >> 5, lane = tid & 31;
    const int lq = lane >> 2;
    const int lr = lane & 3;
    const int wr = warp * 16;

    const int l15 = lane & 15;
    const int lc8 = (lane >> 4) << 3;

    uint32_t kb[2][4], vbb[2];
    #pragma unroll
    for (int bf = 0; bf < 2; bf++) {
        const int kh = bf ? SK1_H : SK0_H;
        const int vh = bf ? SV1_H : SV0_H;
        #pragma unroll
        for (int p = 0; p < 4; p++)
            kb[bf][p] = sb + 2 * (kh + (p * 16 + l15) * KS + lc8);
        vbb[bf] = sb + 2 * (vh + l15 * VS + lc8);
    }

    const __half* qg = Qh + ((size_t)b * SLEN + (size_t)qt * TQ) * DDIM;
    const __half* kgb = Th + (size_t)b * SLEN * DDIM;
    const __half* vgb = Vh + (size_t)b * SLEN * DDIM;
    const int nkt = qt + 1;
    const int grlo = qt * TQ + wr + lq;
    const int grhi = grlo + 8;

    // ---- prologue: Q (staged in SK1) + K0 + V0 ----
    #pragma unroll
    for (int it = 0; it < 8; it++) {
        int i = it * THREADS + tid;
        int r = i >> 4, c = i & 15;
        cp16(sb + 2 * (SK1_H + r * QS + c * 8), qg + (size_t)r * DDIM + c * 8);
        cp16(sb + 2 * (SK0_H + r * KS + c * 8), kgb + (size_t)r * DDIM + c * 8);
        cp16(sb + 2 * (SV0_H + r * VS + c * 8), vgb + (size_t)r * DDIM + c * 8);
    }
    CP_COMMIT();
    CP_WAIT0();
    __syncthreads();

    // Q fragments: register-resident (32 regs)
    uint32_t QF[8][4];
    {
        const uint32_t qa = sb + 2 * (SK1_H + (wr + l15) * QS + lc8);
        #pragma unroll
        for (int ks = 0; ks < 8; ks++) ldsm4(QF[ks], qa + 32u * ks);
    }
    __syncthreads();    // QF reads complete before K(1) overwrites the staging buffer

    // issue K(1) into buffer 1
    if (nkt > 1) {
        const __half* kg = kgb + (size_t)TK * DDIM;
        #pragma unroll
        for (int it = 0; it < 8; it++) {
            int i = it * THREADS + tid;
            int r = i >> 4, c = i & 15;
            cp16(sb + 2 * (SK1_H + r * KS + c * 8), kg + (size_t)r * DDIM + c * 8);
        }
    }
    CP_COMMIT();

    float Oa[16][4];
    #pragma unroll
    for (int nt = 0; nt < 16; nt++)
        #pragma unroll
        for (int k = 0; k < 4; k++) Oa[nt][k] = 0.0f;
    float rslo = 0.0f, rshi = 0.0f;

    // ---- QK(0) + epilogue(0) -> P(0) (unoverlapped, once) ----
    uint32_t PL[8], PH[8];
    {
        float S[8][4];
        #pragma unroll
        for (int nt = 0; nt < 8; nt++)
            #pragma unroll
            for (int k = 0; k < 4; k++) S[nt][k] = 0.0f;
        #pragma unroll
        for (int ks = 0; ks < 8; ks++) {
            const uint32_t ko = 32u * ks;
            #pragma unroll
            for (int p = 0; p < 4; p++) {
                uint32_t B[4];
                ldsm4(B, kb[0][p] + ko);
                mma16(S[2 * p + 0], QF[ks][0], QF[ks][1], QF[ks][2], QF[ks][3], B[0], B[2]);
                mma16(S[2 * p + 1], QF[ks][0], QF[ks][1], QF[ks][2], QF[ks][3], B[1], B[3]);
            }
        }
        __half2 accLo = __float2half2_rn(0.0f);
        __half2 accHi = __float2half2_rn(0.0f);
        #pragma unroll
        for (int nt = 0; nt < 8; nt++)
            epi_nt(S[nt], 0, nt, qt, lr, grlo, grhi, PL[nt], PH[nt], accLo, accHi);
        float2 fl = __half22float2(accLo);
        float2 fh = __half22float2(accHi);
        rslo += fl.x + fl.y;
        rshi += fh.x + fh.y;
    }

    // ---- pipelined mainloop: iteration i does QK(i+1) then {epilogue(i+1) || PV(i)} ----
    for (int i = 0; i < nkt; i++) {
        const int kvb = i & 1;             // V(i) buffer
        const int knb = (i + 1) & 1;       // K(i+1) buffer
        const bool qk_next = (i + 1 < nkt);
        CP_WAIT0();                        // K(i+1), V(i+1)... actually {K(i+1),V(i)} chain resolved
        __syncthreads();                   // prior-iteration buffer reads complete

        // prefetch K(i+2) into buffer i&1 (K(i) dead since iteration i-1)
        if (i + 2 < nkt) {
            const uint32_t skb = sb + 2 * ((i & 1) ? SK1_H : SK0_H);
            const __half* kg = kgb + (size_t)(i + 2) * TK * DDIM;
            #pragma unroll
            for (int it = 0; it < 8; it++) {
                int ii = it * THREADS + tid;
                int r = ii >> 4, c = ii & 15;
                cp16(skb + 2 * (r * KS + c * 8), kg + (size_t)r * DDIM + c * 8);
            }
        }

        // ---- QK(i+1) ----
        float S[8][4];
        if (qk_next) {
            #pragma unroll
            for (int nt = 0; nt < 8; nt++)
                #pragma unroll
                for (int k = 0; k < 4; k++) S[nt][k] = 0.0f;
            #pragma unroll
            for (int ks = 0; ks < 8; ks++) {
                const uint32_t ko = 32u * ks;
                #pragma unroll
                for (int p = 0; p < 4; p++) {
                    uint32_t B[4];
                    ldsm4(B, kb[knb][p] + ko);
                    mma16(S[2 * p + 0], QF[ks][0], QF[ks][1], QF[ks][2], QF[ks][3], B[0], B[2]);
                    mma16(S[2 * p + 1], QF[ks][0], QF[ks][1], QF[ks][2], QF[ks][3], B[1], B[3]);
                }
            }
        }

        // prefetch V(i+1) into buffer (i+1)&1 (V(i-1) dead since iteration i-1)
        if (qk_next) {
            const uint32_t svb = sb + 2 * (((i + 1) & 1) ? SV1_H : SV0_H);
            const __half* vg = vgb + (size_t)(i + 1) * TK * DDIM;
            #pragma unroll
            for (int it = 0; it < 8; it++) {
                int ii = it * THREADS + tid;
                int r = ii >> 4, c = ii & 15;
                cp16(svb + 2 * (r * VS + c * 8), vg + (size_t)r * DDIM + c * 8);
            }
        }
        CP_COMMIT();

        // ---- interleaved: epilogue(i+1) (independent) + PV(i) (uses P(i)) ----
        uint32_t NPL[8], NPH[8];
        __half2 accLo = __float2half2_rn(0.0f);
        __half2 accHi = __float2half2_rn(0.0f);
        #pragma unroll
        for (int ks = 0; ks < 4; ks++) {
            if (qk_next) {
                epi_nt(S[2 * ks + 0], i + 1, 2 * ks + 0, qt, lr, grlo, grhi,
                       NPL[2 * ks + 0], NPH[2 * ks + 0], accLo, accHi);
                epi_nt(S[2 * ks + 1], i + 1, 2 * ks + 1, qt, lr, grlo, grhi,
                       NPL[2 * ks + 1], NPH[2 * ks + 1], accLo, accHi);
            }
            const uint32_t ko = 4352u * ks;   // 16 k-rows * 136 halves * 2B
            const uint32_t a0 = PL[2 * ks], a1 = PH[2 * ks];
            const uint32_t a2 = PL[2 * ks + 1], a3 = PH[2 * ks + 1];
            #pragma unroll
            for (int p = 0; p < 8; p++) {
                uint32_t B[4];
                ldsm4t(B, vbb[kvb] + ko + 32u * p);
                mma16(Oa[2 * p + 0], a0, a1, a2, a3, B[0], B[1]);
                mma16(Oa[2 * p + 1], a0, a1, a2, a3, B[2], B[3]);
            }
        }
        if (qk_next) {
            float2 fl = __half22float2(accLo);
            float2 fh = __half22float2(accHi);
            rslo += fl.x + fl.y;
            rshi += fh.x + fh.y;
            #pragma unroll
            for (int t = 0; t < 8; t++) { PL[t] = NPL[t]; PH[t] = NPH[t]; }
        }
    }

    // ---- rowsum reduce within quad ----
    rslo += __shfl_xor_sync(0xffffffffu, rslo, 1);
    rslo += __shfl_xor_sync(0xffffffffu, rslo, 2);
    rshi += __shfl_xor_sync(0xffffffffu, rshi, 1);
    rshi += __shfl_xor_sync(0xffffffffu, rshi, 2);
    const float invlo = 1.0f / rslo;
    const float invhi = 1.0f / rshi;

    // ---- normalize + store ----
    float* outb = Og + ((size_t)b * SLEN + (size_t)qt * TQ) * DDIM;
    const int rlo = wr + lq;
    const int rhi = rlo + 8;
    #pragma unroll
    for (int nt = 0; nt < 16; nt++) {
        const int c = nt * 8 + lr * 2;
        *(float2*)(outb + (size_t)rlo * DDIM + c) =
            make_float2(Oa[nt][0] * invlo, Oa[nt][1] * invlo);
        *(float2*)(outb + (size_t)rhi * DDIM + c) =
            make_float2(Oa[nt][2] * invhi, Oa[nt][3] * invhi);
    }
}

extern "C" void kernel_launch(void* const* d_in, const int* in_sizes, int n_in,
                              void* d_out, int out_size) {
    (void)in_sizes; (void)n_in; (void)out_size;
    const float* Q = (const float*)d_in[0];
    const float* T = (const float*)d_in[1];
    const float* V = (const float*)d_in[2];
    float* O = (float*)d_out;

    __half *qh, *th, *vh;
    cudaGetSymbolAddress((void**)&qh, g_Qh);
    cudaGetSymbolAddress((void**)&th, g_Th);
    cudaGetSymbolAddress((void**)&vh, g_Vh);

    const int n8 = NB * SLEN * DDIM / 8;
    dim3 cgrid(n8 / 256, 3);
    convAll<<<cgrid, 256>>>(Q, T, V, qh, th, vh);

    cudaFuncSetAttribute(attn_h, cudaFuncAttributeMaxDynamicSharedMemorySize, SMEM_BYTES);
    attn_h<<<(SLEN / TQ) * NB, THREADS, SMEM_BYTES>>>(qh, th, vh, O);
}

// round 15
// speedup vs baseline: 1.0907x; 1.0907x over previous
#include <cuda_runtime.h>
#include <cuda_fp16.h>
#include <cstdint>

#define SLEN 2048
#define DDIM 128
#define NB 16
#define TQ 64
#define TK 64
#define THREADS 128

// strides in halves
#define QS 136
#define KS 136
#define VS 136

// smem offsets in halves: K double + V double (Q in registers, staged via SK1)
#define SK0_H 0
#define SK1_H 8704
#define SV0_H 17408
#define SV1_H 26112
#define SMEM_BYTES (34816 * 2)     // 69632 B

static __device__ __half g_Qh[(size_t)NB * SLEN * DDIM];
static __device__ __half g_Th[(size_t)NB * SLEN * DDIM];
static __device__ __half g_Vh[(size_t)NB * SLEN * DDIM];

__device__ __forceinline__ uint32_t smem_u32(const void* p) {
    uint32_t a;
    asm("{ .reg .u64 t; cvta.to.shared.u64 t, %1; cvt.u32.u64 %0, t; }" : "=r"(a) : "l"(p));
    return a;
}
__device__ __forceinline__ void cp16(uint32_t dst, const void* src) {
    asm volatile("cp.async.cg.shared.global [%0], [%1], 16;" :: "r"(dst), "l"(src) : "memory");
}
#define CP_COMMIT() asm volatile("cp.async.commit_group;" ::: "memory")
#define CP_WAIT0()  asm volatile("cp.async.wait_group 0;" ::: "memory")

__device__ __forceinline__ void ldsm4(uint32_t* r, uint32_t a) {
    asm volatile("ldmatrix.sync.aligned.m8n8.x4.shared.b16 {%0,%1,%2,%3}, [%4];"
                 : "=r"(r[0]), "=r"(r[1]), "=r"(r[2]), "=r"(r[3]) : "r"(a));
}
__device__ __forceinline__ void ldsm4t(uint32_t* r, uint32_t a) {
    asm volatile("ldmatrix.sync.aligned.m8n8.x4.trans.shared.b16 {%0,%1,%2,%3}, [%4];"
                 : "=r"(r[0]), "=r"(r[1]), "=r"(r[2]), "=r"(r[3]) : "r"(a));
}
__device__ __forceinline__ void mma16(float* d, uint32_t a0, uint32_t a1, uint32_t a2,
                                      uint32_t a3, uint32_t b0, uint32_t b1) {
    asm volatile("mma.sync.aligned.m16n8k16.row.col.f32.f16.f16.f32 "
                 "{%0,%1,%2,%3}, {%4,%5,%6,%7}, {%8,%9}, {%0,%1,%2,%3};"
                 : "+f"(d[0]), "+f"(d[1]), "+f"(d[2]), "+f"(d[3])
                 : "r"(a0), "r"(a1), "r"(a2), "r"(a3), "r"(b0), "r"(b1));
}
__device__ __forceinline__ uint32_t ex2h2(uint32_t u) {
    uint32_t r;
    asm("ex2.approx.f16x2 %0, %1;" : "=r"(r) : "r"(u));
    return r;
}

#define CEXC 0.12751754f    // log2(e)/sqrt(128)
#define BIGNC (-30000.0f)

// ---------------- fused conversion pre-kernel (Q, T, V -> fp16) ----------------
__global__ void convAll(const float* __restrict__ Q, const float* __restrict__ T,
                        const float* __restrict__ V,
                        __half* __restrict__ Qh, __half* __restrict__ Th,
                        __half* __restrict__ Vh) {
    const float* s;
    __half* d;
    if (blockIdx.y == 0)      { s = Q; d = Qh; }
    else if (blockIdx.y == 1) { s = T; d = Th; }
    else                      { s = V; d = Vh; }
    int i = blockIdx.x * blockDim.x + threadIdx.x;    // i < n/8
    float4 v0 = ((const float4*)s)[2 * i + 0];
    float4 v1 = ((const float4*)s)[2 * i + 1];
    __half2 h0 = __floats2half2_rn(v0.x, v0.y);
    __half2 h1 = __floats2half2_rn(v0.z, v0.w);
    __half2 h2 = __floats2half2_rn(v1.x, v1.y);
    __half2 h3 = __floats2half2_rn(v1.z, v1.w);
    uint4 o = make_uint4(*(uint32_t*)&h0, *(uint32_t*)&h1,
                         *(uint32_t*)&h2, *(uint32_t*)&h3);
    ((uint4*)d)[i] = o;
}

// epilogue for one n-tile (8 cols): threshold + causal + f16x2 exp2
__device__ __forceinline__ void epi_nt(const float* Snt, int ktile, int nt, int qtv,
                                       int lr, int grlo, int grhi,
                                       uint32_t& plo, uint32_t& phi,
                                       __half2& accLo, __half2& accHi) {
    const int c = nt * 8 + lr * 2;
    const int gc = ktile * TK + c;
    const bool diag = (ktile == qtv);
    float l0 = (Snt[0] > 0.3f) ? Snt[0] * CEXC : 0.0f;
    float l1 = (Snt[1] > 0.3f) ? Snt[1] * CEXC : 0.0f;
    float l2 = (Snt[2] > 0.3f) ? Snt[2] * CEXC : 0.0f;
    float l3 = (Snt[3] > 0.3f) ? Snt[3] * CEXC : 0.0f;
    if (diag) {
        if (gc     > grlo) l0 = BIGNC;
        if (gc + 1 > grlo) l1 = BIGNC;
        if (gc     > grhi) l2 = BIGNC;
        if (gc + 1 > grhi) l3 = BIGNC;
    }
    __half2 hlo = __floats2half2_rn(l0, l1);
    __half2 hhi = __floats2half2_rn(l2, l3);
    plo = ex2h2(*(uint32_t*)&hlo);
    phi = ex2h2(*(uint32_t*)&hhi);
    accLo = __hadd2(accLo, *(__half2*)&plo);
    accHi = __hadd2(accHi, *(__half2*)&phi);
}

// ---------------- main attention kernel ----------------
__global__ __launch_bounds__(THREADS, 2)
void attn_h(const __half* __restrict__ Qh, const __half* __restrict__ Th,
            const __half* __restrict__ Vh, float* __restrict__ Og) {
    extern __shared__ __align__(16) char smraw[];
    const uint32_t sb = smem_u32(smraw);

    const int idx = blockIdx.x;
    const int qt = (SLEN / TQ - 1) - (idx >> 4);   // LPT: heavy first
    const int b = idx & 15;

    const int tid = threadIdx.x;
    const int warp = tid >> 5, lane = tid & 31;
    const int lq = lane >> 2;
    const int lr = lane & 3;
    const int wr = warp * 16;

    const int l15 = lane & 15;
    const int lc8 = (lane >> 4) << 3;

    uint32_t kb[2][4], vbb[2];
    #pragma unroll
    for (int bf = 0; bf < 2; bf++) {
        const int kh = bf ? SK1_H : SK0_H;
        const int vh = bf ? SV1_H : SV0_H;
        #pragma unroll
        for (int p = 0; p < 4; p++)
            kb[bf][p] = sb + 2 * (kh + (p * 16 + l15) * KS + lc8);
        vbb[bf] = sb + 2 * (vh + l15 * VS + lc8);
    }

    const __half* qg = Qh + ((size_t)b * SLEN + (size_t)qt * TQ) * DDIM;
    const __half* kgb = Th + (size_t)b * SLEN * DDIM;
    const __half* vgb = Vh + (size_t)b * SLEN * DDIM;
    const int nkt = qt + 1;
    const int grlo = qt * TQ + wr + lq;
    const int grhi = grlo + 8;

    // ---- prologue: Q (staged in SK1) + K0 + V0 ----
    #pragma unroll
    for (int it = 0; it < 8; it++) {
        int i = it * THREADS + tid;
        int r = i >> 4, c = i & 15;
        cp16(sb + 2 * (SK1_H + r * QS + c * 8), qg + (size_t)r * DDIM + c * 8);
        cp16(sb + 2 * (SK0_H + r * KS + c * 8), kgb + (size_t)r * DDIM + c * 8);
        cp16(sb + 2 * (SV0_H + r * VS + c * 8), vgb + (size_t)r * DDIM + c * 8);
    }
    CP_COMMIT();
    CP_WAIT0();
    __syncthreads();

    // Q fragments: register-resident (32 regs)
    uint32_t QF[8][4];
    {
        const uint32_t qa = sb + 2 * (SK1_H + (wr + l15) * QS + lc8);
        #pragma unroll
        for (int ks = 0; ks < 8; ks++) ldsm4(QF[ks], qa + 32u * ks);
    }

    float Oa[16][4];
    #pragma unroll
    for (int nt = 0; nt < 16; nt++)
        #pragma unroll
        for (int k = 0; k < 4; k++) Oa[nt][k] = 0.0f;
    float rslo = 0.0f, rshi = 0.0f;

    for (int kt = 0; kt < nkt; kt++) {
        const int bf = kt & 1;
        CP_WAIT0();
        __syncthreads();    // K/V(kt) published; bf^1 buffers free (QF read done @kt=0)

        // ---- issue K(kt+1) prefetch now (de-batched from V) ----
        const bool more = (kt + 1 < nkt);
        const __half* kg = kgb + (size_t)(kt + 1) * TK * DDIM;
        const __half* vg = vgb + (size_t)(kt + 1) * TK * DDIM;
        const uint32_t skb = sb + 2 * ((bf ^ 1) ? SK1_H : SK0_H);
        const uint32_t svb = sb + 2 * ((bf ^ 1) ? SV1_H : SV0_H);
        if (more) {
            #pragma unroll
            for (int it = 0; it < 8; it++) {
                int i = it * THREADS + tid;
                int r = i >> 4, c = i & 15;
                cp16(skb + 2 * (r * KS + c * 8), kg + (size_t)r * DDIM + c * 8);
            }
        }

        // ---- fused chunk loop: {QK chunk p} -> {epi chunk p} -> {PV chunk p} ----
        __half2 accLo = __float2half2_rn(0.0f);
        __half2 accHi = __float2half2_rn(0.0f);

        #pragma unroll
        for (int p = 0; p < 4; p++) {
            // QK chunk p: S columns 16p..16p+15 (n-tiles 2p, 2p+1)
            float S2[2][4];
            #pragma unroll
            for (int h = 0; h < 2; h++)
                #pragma unroll
                for (int k = 0; k < 4; k++) S2[h][k] = 0.0f;
            #pragma unroll
            for (int ks = 0; ks < 8; ks++) {
                uint32_t B[4];
                ldsm4(B, kb[bf][p] + 32u * ks);
                mma16(S2[0], QF[ks][0], QF[ks][1], QF[ks][2], QF[ks][3], B[0], B[2]);
                mma16(S2[1], QF[ks][0], QF[ks][1], QF[ks][2], QF[ks][3], B[1], B[3]);
            }

            // V(kt+1) prefetch issued mid-tile so commit->wait distance stays large
            if (p == 1) {
                if (more) {
                    #pragma unroll
                    for (int it = 0; it < 8; it++) {
                        int i = it * THREADS + tid;
                        int r = i >> 4, c = i & 15;
                        cp16(svb + 2 * (r * VS + c * 8), vg + (size_t)r * DDIM + c * 8);
                    }
                }
                CP_COMMIT();   // covers K(kt+1) + V(kt+1)
            }

            // epilogue chunk p
            uint32_t pl0, ph0, pl1, ph1;
            epi_nt(S2[0], kt, 2 * p + 0, qt, lr, grlo, grhi, pl0, ph0, accLo, accHi);
            epi_nt(S2[1], kt, 2 * p + 1, qt, lr, grlo, grhi, pl1, ph1, accLo, accHi);

            // PV chunk p: k-rows 16p..16p+15
            const uint32_t ko = 4352u * p;   // 16 k-rows * 136 halves * 2B
            #pragma unroll
            for (int q8 = 0; q8 < 8; q8++) {
                uint32_t B[4];
                ldsm4t(B, vbb[bf] + ko + 32u * q8);
                mma16(Oa[2 * q8 + 0], pl0, ph0, pl1, ph1, B[0], B[1]);
                mma16(Oa[2 * q8 + 1], pl0, ph0, pl1, ph1, B[2], B[3]);
            }
        }

        {
            float2 fl = __half22float2(accLo);
            float2 fh = __half22float2(accHi);
            rslo += fl.x + fl.y;
            rshi += fh.x + fh.y;
        }
    }

    // ---- rowsum reduce within quad (warp-exclusive rows) ----
    rslo += __shfl_xor_sync(0xffffffffu, rslo, 1);
    rslo += __shfl_xor_sync(0xffffffffu, rslo, 2);
    rshi += __shfl_xor_sync(0xffffffffu, rshi, 1);
    rshi += __shfl_xor_sync(0xffffffffu, rshi, 2);
    const float invlo = 1.0f / rslo;
    const float invhi = 1.0f / rshi;

    // ---- normalize + store ----
    float* outb = Og + ((size_t)b * SLEN + (size_t)qt * TQ) * DDIM;
    const int rlo = wr + lq;
    const int rhi = rlo + 8;
    #pragma unroll
    for (int nt = 0; nt < 16; nt++) {
        const int c = nt * 8 + lr * 2;
        *(float2*)(outb + (size_t)rlo * DDIM + c) =
            make_float2(Oa[nt][0] * invlo, Oa[nt][1] * invlo);
        *(float2*)(outb + (size_t)rhi * DDIM + c) =
            make_float2(Oa[nt][2] * invhi, Oa[nt][3] * invhi);
    }
}

extern "C" void kernel_launch(void* const* d_in, const int* in_sizes, int n_in,
                              void* d_out, int out_size) {
    (void)in_sizes; (void)n_in; (void)out_size;
    const float* Q = (const float*)d_in[0];
    const float* T = (const float*)d_in[1];
    const float* V = (const float*)d_in[2];
    float* O = (float*)d_out;

    __half *qh, *th, *vh;
    cudaGetSymbolAddress((void**)&qh, g_Qh);
    cudaGetSymbolAddress((void**)&th, g_Th);
    cudaGetSymbolAddress((void**)&vh, g_Vh);

    const int n8 = NB * SLEN * DDIM / 8;
    dim3 cgrid(n8 / 256, 3);
    convAll<<<cgrid, 256>>>(Q, T, V, qh, th, vh);

    cudaFuncSetAttribute(attn_h, cudaFuncAttributeMaxDynamicSharedMemorySize, SMEM_BYTES);
    attn_h<<<(SLEN / TQ) * NB, THREADS, SMEM_BYTES>>>(qh, th, vh, O);
}

// round 17
// speedup vs baseline: 1.0918x; 1.0009x over previous
#include <cuda_runtime.h>
#include <cuda_fp16.h>
#include <cstdint>

#define SLEN 2048
#define DDIM 128
#define NB 16
#define TQ 64
#define TK 64
#define THREADS 128

// strides in halves
#define QS 136
#define KS 136
#define VS 136

// smem offsets in halves: K double + V double (Q in registers, staged via SK1)
#define SK0_H 0
#define SK1_H 8704
#define SV0_H 17408
#define SV1_H 26112
#define SMEM_BYTES (34816 * 2)     // 69632 B

static __device__ __half g_Qh[(size_t)NB * SLEN * DDIM];
static __device__ __half g_Th[(size_t)NB * SLEN * DDIM];
static __device__ __half g_Vh[(size_t)NB * SLEN * DDIM];

__device__ __forceinline__ uint32_t smem_u32(const void* p) {
    uint32_t a;
    asm("{ .reg .u64 t; cvta.to.shared.u64 t, %1; cvt.u32.u64 %0, t; }" : "=r"(a) : "l"(p));
    return a;
}
__device__ __forceinline__ void cp16(uint32_t dst, const void* src) {
    asm volatile("cp.async.cg.shared.global [%0], [%1], 16;" :: "r"(dst), "l"(src) : "memory");
}
#define CP_COMMIT() asm volatile("cp.async.commit_group;" ::: "memory")
#define CP_WAIT0()  asm volatile("cp.async.wait_group 0;" ::: "memory")

__device__ __forceinline__ void ldsm4(uint32_t* r, uint32_t a) {
    asm volatile("ldmatrix.sync.aligned.m8n8.x4.shared.b16 {%0,%1,%2,%3}, [%4];"
                 : "=r"(r[0]), "=r"(r[1]), "=r"(r[2]), "=r"(r[3]) : "r"(a));
}
__device__ __forceinline__ void ldsm4t(uint32_t* r, uint32_t a) {
    asm volatile("ldmatrix.sync.aligned.m8n8.x4.trans.shared.b16 {%0,%1,%2,%3}, [%4];"
                 : "=r"(r[0]), "=r"(r[1]), "=r"(r[2]), "=r"(r[3]) : "r"(a));
}
// NOTE: non-volatile — HMMA is a pure register op; let ptxas schedule globally.
__device__ __forceinline__ void mma16(float* d, uint32_t a0, uint32_t a1, uint32_t a2,
                                      uint32_t a3, uint32_t b0, uint32_t b1) {
    asm("mma.sync.aligned.m16n8k16.row.col.f32.f16.f16.f32 "
        "{%0,%1,%2,%3}, {%4,%5,%6,%7}, {%8,%9}, {%0,%1,%2,%3};"
        : "+f"(d[0]), "+f"(d[1]), "+f"(d[2]), "+f"(d[3])
        : "r"(a0), "r"(a1), "r"(a2), "r"(a3), "r"(b0), "r"(b1));
}
__device__ __forceinline__ uint32_t ex2h2(uint32_t u) {
    uint32_t r;
    asm("ex2.approx.f16x2 %0, %1;" : "=r"(r) : "r"(u));
    return r;
}

#define CEXC 0.12751754f    // log2(e)/sqrt(128)
#define BIGNC (-30000.0f)

// ---------------- fused conversion pre-kernel (Q, T, V -> fp16) ----------------
__global__ void convAll(const float* __restrict__ Q, const float* __restrict__ T,
                        const float* __restrict__ V,
                        __half* __restrict__ Qh, __half* __restrict__ Th,
                        __half* __restrict__ Vh) {
    const float* s;
    __half* d;
    if (blockIdx.y == 0)      { s = Q; d = Qh; }
    else if (blockIdx.y == 1) { s = T; d = Th; }
    else                      { s = V; d = Vh; }
    int i = blockIdx.x * blockDim.x + threadIdx.x;    // i < n/8
    float4 v0 = ((const float4*)s)[2 * i + 0];
    float4 v1 = ((const float4*)s)[2 * i + 1];
    __half2 h0 = __floats2half2_rn(v0.x, v0.y);
    __half2 h1 = __floats2half2_rn(v0.z, v0.w);
    __half2 h2 = __floats2half2_rn(v1.x, v1.y);
    __half2 h3 = __floats2half2_rn(v1.z, v1.w);
    uint4 o = make_uint4(*(uint32_t*)&h0, *(uint32_t*)&h1,
                         *(uint32_t*)&h2, *(uint32_t*)&h3);
    ((uint4*)d)[i] = o;
}

// epilogue, non-diagonal tile: threshold + f16x2 exp2 (no causal checks)
__device__ __forceinline__ void epi_nd(const float* Snt,
                                       uint32_t& plo, uint32_t& phi,
                                       __half2& accLo, __half2& accHi) {
    float l0 = (Snt[0] > 0.3f) ? Snt[0] * CEXC : 0.0f;
    float l1 = (Snt[1] > 0.3f) ? Snt[1] * CEXC : 0.0f;
    float l2 = (Snt[2] > 0.3f) ? Snt[2] * CEXC : 0.0f;
    float l3 = (Snt[3] > 0.3f) ? Snt[3] * CEXC : 0.0f;
    __half2 hlo = __floats2half2_rn(l0, l1);
    __half2 hhi = __floats2half2_rn(l2, l3);
    plo = ex2h2(*(uint32_t*)&hlo);
    phi = ex2h2(*(uint32_t*)&hhi);
    accLo = __hadd2(accLo, *(__half2*)&plo);
    accHi = __hadd2(accHi, *(__half2*)&phi);
}

// epilogue, diagonal tile: causal reduces to LOCAL col-vs-row compares (kt==qt, TQ==TK)
__device__ __forceinline__ void epi_d(const float* Snt, int c, int llo, int lhi,
                                      uint32_t& plo, uint32_t& phi,
                                      __half2& accLo, __half2& accHi) {
    float l0 = (Snt[0] > 0.3f) ? Snt[0] * CEXC : 0.0f;
    float l1 = (Snt[1] > 0.3f) ? Snt[1] * CEXC : 0.0f;
    float l2 = (Snt[2] > 0.3f) ? Snt[2] * CEXC : 0.0f;
    float l3 = (Snt[3] > 0.3f) ? Snt[3] * CEXC : 0.0f;
    if (c     > llo) l0 = BIGNC;
    if (c + 1 > llo) l1 = BIGNC;
    if (c     > lhi) l2 = BIGNC;
    if (c + 1 > lhi) l3 = BIGNC;
    __half2 hlo = __floats2half2_rn(l0, l1);
    __half2 hhi = __floats2half2_rn(l2, l3);
    plo = ex2h2(*(uint32_t*)&hlo);
    phi = ex2h2(*(uint32_t*)&hhi);
    accLo = __hadd2(accLo, *(__half2*)&plo);
    accHi = __hadd2(accHi, *(__half2*)&phi);
}

// ---------------- main attention kernel ----------------
__global__ __launch_bounds__(THREADS, 2)
void attn_h(const __half* __restrict__ Qh, const __half* __restrict__ Th,
            const __half* __restrict__ Vh, float* __restrict__ Og) {
    extern __shared__ __align__(16) char smraw[];
    const uint32_t sb = smem_u32(smraw);

    const int idx = blockIdx.x;
    const int qt = (SLEN / TQ - 1) - (idx >> 4);   // LPT: heavy first
    const int b = idx & 15;

    const int tid = threadIdx.x;
    const int warp = tid >> 5, lane = tid & 31;
    const int lq = lane >> 2;
    const int lr = lane & 3;
    const int wr = warp * 16;

    const int l15 = lane & 15;
    const int lc8 = (lane >> 4) << 3;

    uint32_t kb[2][4], vbb[2];
    #pragma unroll
    for (int bf = 0; bf < 2; bf++) {
        const int kh = bf ? SK1_H : SK0_H;
        const int vh = bf ? SV1_H : SV0_H;
        #pragma unroll
        for (int p = 0; p < 4; p++)
            kb[bf][p] = sb + 2 * (kh + (p * 16 + l15) * KS + lc8);
        vbb[bf] = sb + 2 * (vh + l15 * VS + lc8);
    }

    const __half* qg = Qh + ((size_t)b * SLEN + (size_t)qt * TQ) * DDIM;
    const __half* kgb = Th + (size_t)b * SLEN * DDIM;
    const __half* vgb = Vh + (size_t)b * SLEN * DDIM;

    // ---- prologue: Q (staged in SK1) + K0 + V0 ----
    #pragma unroll
    for (int it = 0; it < 8; it++) {
        int i = it * THREADS + tid;
        int r = i >> 4, c = i & 15;
        cp16(sb + 2 * (SK1_H + r * QS + c * 8), qg + (size_t)r * DDIM + c * 8);
        cp16(sb + 2 * (SK0_H + r * KS + c * 8), kgb + (size_t)r * DDIM + c * 8);
        cp16(sb + 2 * (SV0_H + r * VS + c * 8), vgb + (size_t)r * DDIM + c * 8);
    }
    CP_COMMIT();
    CP_WAIT0();
    __syncthreads();

    // Q fragments: register-resident (32 regs)
    uint32_t QF[8][4];
    {
        const uint32_t qa = sb + 2 * (SK1_H + (wr + l15) * QS + lc8);
        #pragma unroll
        for (int ks = 0; ks < 8; ks++) ldsm4(QF[ks], qa + 32u * ks);
    }

    float Oa[16][4];
    #pragma unroll
    for (int nt = 0; nt < 16; nt++)
        #pragma unroll
        for (int k = 0; k < 4; k++) Oa[nt][k] = 0.0f;
    float rslo = 0.0f, rshi = 0.0f;

    // ---- mainloop: non-diagonal tiles kt = 0 .. qt-1 (next tile always exists) ----
    for (int kt = 0; kt < qt; kt++) {
        const int bf = kt & 1;
        CP_WAIT0();
        __syncthreads();    // K/V(kt) published; bf^1 buffers free (QF read done @kt=0)

        // issue K(kt+1) prefetch now (de-batched from V)
        const __half* kg = kgb + (size_t)(kt + 1) * TK * DDIM;
        const __half* vg = vgb + (size_t)(kt + 1) * TK * DDIM;
        const uint32_t skb = sb + 2 * ((bf ^ 1) ? SK1_H : SK0_H);
        const uint32_t svb = sb + 2 * ((bf ^ 1) ? SV1_H : SV0_H);
        #pragma unroll
        for (int it = 0; it < 8; it++) {
            int i = it * THREADS + tid;
            int r = i >> 4, c = i & 15;
            cp16(skb + 2 * (r * KS + c * 8), kg + (size_t)r * DDIM + c * 8);
        }

        __half2 accLo = __float2half2_rn(0.0f);
        __half2 accHi = __float2half2_rn(0.0f);

        #pragma unroll
        for (int p = 0; p < 4; p++) {
            // QK chunk p (n-tiles 2p, 2p+1)
            float S2[2][4];
            #pragma unroll
            for (int h = 0; h < 2; h++)
                #pragma unroll
                for (int k = 0; k < 4; k++) S2[h][k] = 0.0f;
            #pragma unroll
            for (int ks = 0; ks < 8; ks++) {
                uint32_t B[4];
                ldsm4(B, kb[bf][p] + 32u * ks);
                mma16(S2[0], QF[ks][0], QF[ks][1], QF[ks][2], QF[ks][3], B[0], B[2]);
                mma16(S2[1], QF[ks][0], QF[ks][1], QF[ks][2], QF[ks][3], B[1], B[3]);
            }

            // V(kt+1) prefetch mid-tile so commit->wait distance stays large
            if (p == 1) {
                #pragma unroll
                for (int it = 0; it < 8; it++) {
                    int i = it * THREADS + tid;
                    int r = i >> 4, c = i & 15;
                    cp16(svb + 2 * (r * VS + c * 8), vg + (size_t)r * DDIM + c * 8);
                }
                CP_COMMIT();   // covers K(kt+1) + V(kt+1)
            }

            // epilogue chunk p (no causal)
            uint32_t pl0, ph0, pl1, ph1;
            epi_nd(S2[0], pl0, ph0, accLo, accHi);
            epi_nd(S2[1], pl1, ph1, accLo, accHi);

            // PV chunk p
            const uint32_t ko = 4352u * p;   // 16 k-rows * 136 halves * 2B
            #pragma unroll
            for (int q8 = 0; q8 < 8; q8++) {
                uint32_t B[4];
                ldsm4t(B, vbb[bf] + ko + 32u * q8);
                mma16(Oa[2 * q8 + 0], pl0, ph0, pl1, ph1, B[0], B[1]);
                mma16(Oa[2 * q8 + 1], pl0, ph0, pl1, ph1, B[2], B[3]);
            }
        }

        float2 fl = __half22float2(accLo);
        float2 fh = __half22float2(accHi);
        rslo += fl.x + fl.y;
        rshi += fh.x + fh.y;
    }

    // ---- peeled diagonal tile kt = qt (causal, no prefetch) ----
    {
        const int bf = qt & 1;
        CP_WAIT0();
        __syncthreads();

        const int llo = wr + lq;
        const int lhi = llo + 8;
        __half2 accLo = __float2half2_rn(0.0f);
        __half2 accHi = __float2half2_rn(0.0f);

        #pragma unroll
        for (int p = 0; p < 4; p++) {
            float S2[2][4];
            #pragma unroll
            for (int h = 0; h < 2; h++)
                #pragma unroll
                for (int k = 0; k < 4; k++) S2[h][k] = 0.0f;
            #pragma unroll
            for (int ks = 0; ks < 8; ks++) {
                uint32_t B[4];
                ldsm4(B, kb[bf][p] + 32u * ks);
                mma16(S2[0], QF[ks][0], QF[ks][1], QF[ks][2], QF[ks][3], B[0], B[2]);
                mma16(S2[1], QF[ks][0], QF[ks][1], QF[ks][2], QF[ks][3], B[1], B[3]);
            }
            uint32_t pl0, ph0, pl1, ph1;
            epi_d(S2[0], (2 * p + 0) * 8 + lr * 2, llo, lhi, pl0, ph0, accLo, accHi);
            epi_d(S2[1], (2 * p + 1) * 8 + lr * 2, llo, lhi, pl1, ph1, accLo, accHi);

            const uint32_t ko = 4352u * p;
            #pragma unroll
            for (int q8 = 0; q8 < 8; q8++) {
                uint32_t B[4];
                ldsm4t(B, vbb[bf] + ko + 32u * q8);
                mma16(Oa[2 * q8 + 0], pl0, ph0, pl1, ph1, B[0], B[1]);
                mma16(Oa[2 * q8 + 1], pl0, ph0, pl1, ph1, B[2], B[3]);
            }
        }

        float2 fl = __half22float2(accLo);
        float2 fh = __half22float2(accHi);
        rslo += fl.x + fl.y;
        rshi += fh.x + fh.y;
    }

    // ---- rowsum reduce within quad (warp-exclusive rows) ----
    rslo += __shfl_xor_sync(0xffffffffu, rslo, 1);
    rslo += __shfl_xor_sync(0xffffffffu, rslo, 2);
    rshi += __shfl_xor_sync(0xffffffffu, rshi, 1);
    rshi += __shfl_xor_sync(0xffffffffu, rshi, 2);
    const float invlo = 1.0f / rslo;
    const float invhi = 1.0f / rshi;

    // ---- normalize + store ----
    float* outb = Og + ((size_t)b * SLEN + (size_t)qt * TQ) * DDIM;
    const int rlo = wr + lq;
    const int rhi = rlo + 8;
    #pragma unroll
    for (int nt = 0; nt < 16; nt++) {
        const int c = nt * 8 + lr * 2;
        *(float2*)(outb + (size_t)rlo * DDIM + c) =
            make_float2(Oa[nt][0] * invlo, Oa[nt][1] * invlo);
        *(float2*)(outb + (size_t)rhi * DDIM + c) =
            make_float2(Oa[nt][2] * invhi, Oa[nt][3] * invhi);
    }
}

extern "C" void kernel_launch(void* const* d_in, const int* in_sizes, int n_in,
                              void* d_out, int out_size) {
    (void)in_sizes; (void)n_in; (void)out_size;
    const float* Q = (const float*)d_in[0];
    const float* T = (const float*)d_in[1];
    const float* V = (const float*)d_in[2];
    float* O = (float*)d_out;

    __half *qh, *th, *vh;
    cudaGetSymbolAddress((void**)&qh, g_Qh);
    cudaGetSymbolAddress((void**)&th, g_Th);
    cudaGetSymbolAddress((void**)&vh, g_Vh);

    const int n8 = NB * SLEN * DDIM / 8;
    dim3 cgrid(n8 / 256, 3);
    convAll<<<cgrid, 256>>>(Q, T, V, qh, th, vh);

    cudaFuncSetAttribute(attn_h, cudaFuncAttributeMaxDynamicSharedMemorySize, SMEM_BYTES);
    attn_h<<<(SLEN / TQ) * NB, THREADS, SMEM_BYTES>>>(qh, th, vh, O);
}